// round 15
// baseline (speedup 1.0000x reference)
#include <cuda_runtime.h>

#define NN   50000
#define FIN  128
#define HID  16
#define EMAX 800000

// Scratch — referenced ONLY inside kernel bodies (never as host-side args!)
// g_cnt is self-restoring: zero at module load; k_out's tail re-zeroes it
// each call, so every invocation sees identical state (deterministic).
static __device__ int   g_cnt [NN];
static __device__ float g_dinv[NN];
static __device__ float g_h1s [NN * HID];   // (x@W1) * dinv[node]
static __device__ float g_agg1[NN * HID];
static __device__ float g_h2s [NN * HID];   // relu(...) * dinv[node]
static __device__ float g_agg2[NN * HID];

// ---------------------------------------------------------------------------
__device__ __forceinline__ void red_add_v4(float* addr, float4 v) {
    asm volatile("red.global.add.v4.f32 [%0], {%1, %2, %3, %4};"
                 :: "l"(addr), "f"(v.x), "f"(v.y), "f"(v.z), "f"(v.w)
                 : "memory");
}

// ---------------------------------------------------------------------------
// 1) in-degree histogram over dst (row 1 of int32 [2,E]) — 4 edges/thread
__global__ void k_deg(const int* __restrict__ ei) {
    int t = blockIdx.x * blockDim.x + threadIdx.x;
    if (t >= EMAX / 4) return;
    int4 d4 = __ldg((const int4*)(ei + EMAX) + t);
    if ((unsigned)d4.x < (unsigned)NN) atomicAdd(&g_cnt[d4.x], 1);
    if ((unsigned)d4.y < (unsigned)NN) atomicAdd(&g_cnt[d4.y], 1);
    if ((unsigned)d4.z < (unsigned)NN) atomicAdd(&g_cnt[d4.z], 1);
    if ((unsigned)d4.w < (unsigned)NN) atomicAdd(&g_cnt[d4.w], 1);
}

// ---------------------------------------------------------------------------
// 2) h1s = (x @ W1) * dinv, dinv = rsqrt(1 + cnt); zeroes agg1/agg2 rows.
//    1 node per thread, all 16 outputs; W1 broadcast from smem; f32x2 FMA.
//    xs stride 33 (odd): bank = (tid + k) & 31 -> conflict-free.
__global__ __launch_bounds__(256) void k_mm1(const float* __restrict__ x,
                                             const float* __restrict__ W1) {
    __shared__ float ws[FIN * HID];     // 8 KB
    __shared__ float xs[256 * 33];      // 33.8 KB (chunk of 32 k-values)
    int node0 = blockIdx.x * 256;
    int tid = threadIdx.x;
    int node = node0 + tid;

    // zero this block's agg rows (runs before scat1 kernel-wide)
    {
        size_t base4 = (size_t)node0 * HID / 4;
        for (int i = tid; i < 256 * HID / 4; i += 256) {
            size_t idx = base4 + i;
            if (idx < (size_t)NN * HID / 4) {
                ((float4*)g_agg1)[idx] = make_float4(0.f, 0.f, 0.f, 0.f);
                ((float4*)g_agg2)[idx] = make_float4(0.f, 0.f, 0.f, 0.f);
            }
        }
    }
    // stage W1 (coalesced float4)
    for (int i4 = tid; i4 < FIN * HID / 4; i4 += 256)
        ((float4*)ws)[i4] = __ldg((const float4*)W1 + i4);

    float dv = 0.f;
    if (node < NN) {
        dv = rsqrtf(1.0f + (float)g_cnt[node]);
        g_dinv[node] = dv;
    }

    unsigned long long acc[8];
    #pragma unroll
    for (int j = 0; j < 8; j++) acc[j] = 0ULL;   // bits of (0.f, 0.f)

    for (int c = 0; c < 4; c++) {
        __syncthreads();
        // stage x chunk: 256 nodes x 32 k, coalesced scalar reads
        for (int i = tid; i < 256 * 32; i += 256) {
            int row = i >> 5, col = i & 31;
            int nd = node0 + row;
            xs[row * 33 + col] =
                (nd < NN) ? __ldg(&x[(size_t)nd * FIN + c * 32 + col]) : 0.f;
        }
        __syncthreads();
        #pragma unroll
        for (int k = 0; k < 32; k++) {
            float xk = xs[tid * 33 + k];
            unsigned long long x2;
            asm("mov.b64 %0, {%1, %1};" : "=l"(x2) : "f"(xk));
            const float4* wrow = (const float4*)&ws[(c * 32 + k) * HID];
            #pragma unroll
            for (int j4 = 0; j4 < 4; j4++) {
                float4 wv = wrow[j4];                       // broadcast LDS.128
                unsigned long long w01, w23;
                asm("mov.b64 %0, {%1, %2};" : "=l"(w01) : "f"(wv.x), "f"(wv.y));
                asm("mov.b64 %0, {%1, %2};" : "=l"(w23) : "f"(wv.z), "f"(wv.w));
                asm("fma.rn.f32x2 %0, %1, %2, %0;" : "+l"(acc[j4 * 2])     : "l"(w01), "l"(x2));
                asm("fma.rn.f32x2 %0, %1, %2, %0;" : "+l"(acc[j4 * 2 + 1]) : "l"(w23), "l"(x2));
            }
        }
    }

    if (node < NN) {
        float o[16];
        #pragma unroll
        for (int j = 0; j < 8; j++) {
            float lo, hi;
            asm("mov.b64 {%0, %1}, %2;" : "=f"(lo), "=f"(hi) : "l"(acc[j]));
            o[2 * j]     = lo * dv;
            o[2 * j + 1] = hi * dv;
        }
        float4* orow = (float4*)(g_h1s + (size_t)node * HID);
        orow[0] = make_float4(o[0],  o[1],  o[2],  o[3]);
        orow[1] = make_float4(o[4],  o[5],  o[6],  o[7]);
        orow[2] = make_float4(o[8],  o[9],  o[10], o[11]);
        orow[3] = make_float4(o[12], o[13], o[14], o[15]);
    }
}

// ---------------------------------------------------------------------------
// 3) layer-1 scatter: agg1[dst] += h1s[src] — 4 edges/thread, MLP-batched (R14)
__global__ void k_scat1(const int* __restrict__ ei) {
    int t = blockIdx.x * blockDim.x + threadIdx.x;
    int q = t & 3;
    int g = t >> 2;
    if (g >= EMAX / 4) return;
    int4 s4 = __ldg((const int4*)ei + g);
    int4 d4 = __ldg((const int4*)(ei + EMAX) + g);
    float4 v0 = ((const float4*)(g_h1s + (size_t)s4.x * HID))[q];
    float4 v1 = ((const float4*)(g_h1s + (size_t)s4.y * HID))[q];
    float4 v2 = ((const float4*)(g_h1s + (size_t)s4.z * HID))[q];
    float4 v3 = ((const float4*)(g_h1s + (size_t)s4.w * HID))[q];
    red_add_v4((float*)((float4*)(g_agg1 + (size_t)d4.x * HID) + q), v0);
    red_add_v4((float*)((float4*)(g_agg1 + (size_t)d4.y * HID) + q), v1);
    red_add_v4((float*)((float4*)(g_agg1 + (size_t)d4.z * HID) + q), v2);
    red_add_v4((float*)((float4*)(g_agg1 + (size_t)d4.w * HID) + q), v3);
}

// ---------------------------------------------------------------------------
// 4) h2s = relu(dinv*(agg1 + h1s) + b1) * dinv
__global__ void k_relu(const float* __restrict__ b1) {
    int i = blockIdx.x * blockDim.x + threadIdx.x;
    if (i < NN * HID) {
        int node = i >> 4, f = i & 15;
        float di = g_dinv[node];
        float t = di * (g_agg1[i] + g_h1s[i]) + __ldg(&b1[f]);
        g_h2s[i] = fmaxf(t, 0.f) * di;
    }
}

// ---------------------------------------------------------------------------
// 5) layer-2 scatter: agg2[dst] += h2s[src]
__global__ void k_scat2(const int* __restrict__ ei) {
    int t = blockIdx.x * blockDim.x + threadIdx.x;
    int q = t & 3;
    int g = t >> 2;
    if (g >= EMAX / 4) return;
    int4 s4 = __ldg((const int4*)ei + g);
    int4 d4 = __ldg((const int4*)(ei + EMAX) + g);
    float4 v0 = ((const float4*)(g_h2s + (size_t)s4.x * HID))[q];
    float4 v1 = ((const float4*)(g_h2s + (size_t)s4.y * HID))[q];
    float4 v2 = ((const float4*)(g_h2s + (size_t)s4.z * HID))[q];
    float4 v3 = ((const float4*)(g_h2s + (size_t)s4.w * HID))[q];
    red_add_v4((float*)((float4*)(g_agg2 + (size_t)d4.x * HID) + q), v0);
    red_add_v4((float*)((float4*)(g_agg2 + (size_t)d4.y * HID) + q), v1);
    red_add_v4((float*)((float4*)(g_agg2 + (size_t)d4.z * HID) + q), v2);
    red_add_v4((float*)((float4*)(g_agg2 + (size_t)d4.w * HID) + q), v3);
}

// ---------------------------------------------------------------------------
// 6) out = (dinv*(agg2 + h2s)) @ W2 + b2 — 64 nodes / 512-thread block (R12).
//    Tail: zero g_cnt rows for the next invocation (self-restoring state).
#define VS_STRIDE 17
__global__ __launch_bounds__(512) void k_out(const float* __restrict__ W2,
                                             const float* __restrict__ b2,
                                             float* __restrict__ out) {
    __shared__ float wsh[HID * FIN];
    __shared__ float vsh[64 * VS_STRIDE];
    __shared__ float b2s[FIN];
    int node0 = blockIdx.x * 64;
    int tid = threadIdx.x;

    for (int i4 = tid; i4 < HID * FIN / 4; i4 += 512)
        ((float4*)wsh)[i4] = __ldg((const float4*)W2 + i4);
    if (tid < FIN) b2s[tid] = __ldg(&b2[tid]);
    for (int i = tid; i < 64 * HID; i += 512) {
        int nl = i >> 4, f = i & 15;
        int node = node0 + nl;
        float v = 0.f;
        if (node < NN) {
            int gi = node * HID + f;
            v = g_dinv[node] * (g_agg2[gi] + g_h2s[gi]);
        }
        vsh[nl * VS_STRIDE + f] = v;
    }
    // tail: reset histogram for next call (no dependency on rest of kernel)
    if (tid < 64) {
        int node = node0 + tid;
        if (node < NN) g_cnt[node] = 0;
    }
    __syncthreads();

    int n = tid >> 3, og = tid & 7;
    int node = node0 + n;
    if (node >= NN) return;

    float acc[4][4];
    #pragma unroll
    for (int j = 0; j < 4; j++)
        #pragma unroll
        for (int i = 0; i < 4; i++)
            acc[j][i] = b2s[og * 4 + 32 * j + i];

    #pragma unroll
    for (int k = 0; k < HID; k++) {
        float v = vsh[n * VS_STRIDE + k];
        #pragma unroll
        for (int j = 0; j < 4; j++) {
            float4 w = *(const float4*)&wsh[k * FIN + og * 4 + 32 * j];
            acc[j][0] += v * w.x;  acc[j][1] += v * w.y;
            acc[j][2] += v * w.z;  acc[j][3] += v * w.w;
        }
    }
    float* orow = out + (size_t)node * FIN;
    #pragma unroll
    for (int j = 0; j < 4; j++)
        *(float4*)&orow[og * 4 + 32 * j] =
            make_float4(acc[j][0], acc[j][1], acc[j][2], acc[j][3]);
}

// ---------------------------------------------------------------------------
extern "C" void kernel_launch(void* const* d_in, const int* in_sizes, int n_in,
                              void* d_out, int out_size) {
    // Binding proven in R9: 0:x  1:edge_index(int32 [2,E])  2:W1  3:b1  4:W2  5:b2
    const float* x  = (const float*)d_in[0];
    const int*   ei = (const int*)d_in[1];
    const float* W1 = (const float*)d_in[2];
    const float* b1 = (const float*)d_in[3];
    const float* W2 = (const float*)d_in[4];
    const float* b2 = (const float*)d_in[5];
    float* out = (float*)d_out;

    k_deg  <<<(EMAX / 4 + 255) / 256, 256>>>(ei);
    k_mm1  <<<(NN + 255) / 256, 256>>>(x, W1);
    k_scat1<<<(EMAX + 255) / 256, 256>>>(ei);
    k_relu <<<(NN * HID + 255) / 256, 256>>>(b1);
    k_scat2<<<(EMAX + 255) / 256, 256>>>(ei);
    k_out  <<<(NN + 63) / 64, 512>>>(W2, b2, out);
}

// round 16
// speedup vs baseline: 1.0222x; 1.0222x over previous
#include <cuda_runtime.h>

#define NN   50000
#define FIN  128
#define HID  16
#define EMAX 800000

// Scratch — referenced ONLY inside kernel bodies (never as host-side args!)
// g_cnt is self-restoring: zero at module load; k_out's tail re-zeroes it
// each call, so every invocation sees identical state (deterministic).
static __device__ int   g_cnt [NN];
static __device__ float g_dinv[NN];
static __device__ float g_h1s [NN * HID];   // (x@W1) * dinv[node]
static __device__ float g_agg1[NN * HID];
static __device__ float g_h2s [NN * HID];   // relu(...) * dinv[node]
static __device__ float g_agg2[NN * HID];

// ---------------------------------------------------------------------------
__device__ __forceinline__ void red_add_v4(float* addr, float4 v) {
    asm volatile("red.global.add.v4.f32 [%0], {%1, %2, %3, %4};"
                 :: "l"(addr), "f"(v.x), "f"(v.y), "f"(v.z), "f"(v.w)
                 : "memory");
}

// ---------------------------------------------------------------------------
// 1) in-degree histogram over dst (row 1 of int32 [2,E]) — 4 edges/thread
__global__ void k_deg(const int* __restrict__ ei) {
    int t = blockIdx.x * blockDim.x + threadIdx.x;
    if (t >= EMAX / 4) return;
    int4 d4 = __ldg((const int4*)(ei + EMAX) + t);
    if ((unsigned)d4.x < (unsigned)NN) atomicAdd(&g_cnt[d4.x], 1);
    if ((unsigned)d4.y < (unsigned)NN) atomicAdd(&g_cnt[d4.y], 1);
    if ((unsigned)d4.z < (unsigned)NN) atomicAdd(&g_cnt[d4.z], 1);
    if ((unsigned)d4.w < (unsigned)NN) atomicAdd(&g_cnt[d4.w], 1);
}

// ---------------------------------------------------------------------------
// 2) h1s = (x @ W1) * dinv, dinv = rsqrt(1+cnt); zeroes this tile's agg rows.
//    R12-proven tiling: 32 nodes / 256 threads; n = tid>>3, og = tid&7.
#define XS_STRIDE 132
__global__ __launch_bounds__(256) void k_mm1(const float* __restrict__ x,
                                             const float* __restrict__ W1) {
    __shared__ float xs[32 * XS_STRIDE];  // 16.5 KB
    __shared__ float ws[FIN * HID];       // 8 KB
    __shared__ float dvs[32];
    int node0 = blockIdx.x * 32;
    int tid = threadIdx.x;

    // zero agg1/agg2 rows of this tile (32 nodes * 16 = 128 float4 each)
    {
        size_t base4 = (size_t)node0 * HID / 4;
        size_t lim4  = (size_t)NN * HID / 4;
        if (tid < 128) {
            size_t idx = base4 + tid;
            if (idx < lim4) ((float4*)g_agg1)[idx] = make_float4(0.f, 0.f, 0.f, 0.f);
        } else {
            size_t idx = base4 + (tid - 128);
            if (idx < lim4) ((float4*)g_agg2)[idx] = make_float4(0.f, 0.f, 0.f, 0.f);
        }
    }
    for (int i4 = tid; i4 < FIN * HID / 4; i4 += 256)
        ((float4*)ws)[i4] = __ldg((const float4*)W1 + i4);
    for (int i4 = tid; i4 < 32 * FIN / 4; i4 += 256) {
        int row = i4 >> 5, col4 = i4 & 31;
        int node = node0 + row;
        float4 v = (node < NN) ? __ldg((const float4*)(x + (size_t)node * FIN) + col4)
                               : make_float4(0.f, 0.f, 0.f, 0.f);
        *(float4*)&xs[row * XS_STRIDE + col4 * 4] = v;
    }
    if (tid < 32) {
        int node = node0 + tid;
        float d = (node < NN) ? rsqrtf(1.0f + (float)g_cnt[node]) : 0.f;
        dvs[tid] = d;
        if (node < NN) g_dinv[node] = d;
    }
    __syncthreads();

    int n = tid >> 3, og = tid & 7;
    int o0 = og * 2;
    float acc0 = 0.f, acc1 = 0.f;
    #pragma unroll
    for (int k4 = 0; k4 < FIN / 4; k4++) {
        float4 xv = *(const float4*)&xs[n * XS_STRIDE + k4 * 4];
        float2 w0 = *(const float2*)&ws[(k4 * 4 + 0) * HID + o0];
        float2 w1 = *(const float2*)&ws[(k4 * 4 + 1) * HID + o0];
        float2 w2 = *(const float2*)&ws[(k4 * 4 + 2) * HID + o0];
        float2 w3 = *(const float2*)&ws[(k4 * 4 + 3) * HID + o0];
        acc0 += xv.x * w0.x + xv.y * w1.x + xv.z * w2.x + xv.w * w3.x;
        acc1 += xv.x * w0.y + xv.y * w1.y + xv.z * w2.y + xv.w * w3.y;
    }
    int node = node0 + n;
    if (node < NN) {
        float dv = dvs[n];
        g_h1s[node * HID + o0]     = acc0 * dv;
        g_h1s[node * HID + o0 + 1] = acc1 * dv;
    }
}

// ---------------------------------------------------------------------------
// 3) layer-1 scatter: agg1[dst] += h1s[src]
//    8 edges per 4-thread group; thread q owns feature quarter q. MLP=8.
__global__ void k_scat1(const int* __restrict__ ei) {
    int t = blockIdx.x * blockDim.x + threadIdx.x;
    int q = t & 3;
    int g = t >> 2;                          // 8-edge group
    if (g >= EMAX / 8) return;
    int4 sa = __ldg((const int4*)ei + g * 2);
    int4 sb = __ldg((const int4*)ei + g * 2 + 1);
    int4 da = __ldg((const int4*)(ei + EMAX) + g * 2);
    int4 db = __ldg((const int4*)(ei + EMAX) + g * 2 + 1);
    float4 v0 = ((const float4*)(g_h1s + (size_t)sa.x * HID))[q];
    float4 v1 = ((const float4*)(g_h1s + (size_t)sa.y * HID))[q];
    float4 v2 = ((const float4*)(g_h1s + (size_t)sa.z * HID))[q];
    float4 v3 = ((const float4*)(g_h1s + (size_t)sa.w * HID))[q];
    float4 v4 = ((const float4*)(g_h1s + (size_t)sb.x * HID))[q];
    float4 v5 = ((const float4*)(g_h1s + (size_t)sb.y * HID))[q];
    float4 v6 = ((const float4*)(g_h1s + (size_t)sb.z * HID))[q];
    float4 v7 = ((const float4*)(g_h1s + (size_t)sb.w * HID))[q];
    red_add_v4((float*)((float4*)(g_agg1 + (size_t)da.x * HID) + q), v0);
    red_add_v4((float*)((float4*)(g_agg1 + (size_t)da.y * HID) + q), v1);
    red_add_v4((float*)((float4*)(g_agg1 + (size_t)da.z * HID) + q), v2);
    red_add_v4((float*)((float4*)(g_agg1 + (size_t)da.w * HID) + q), v3);
    red_add_v4((float*)((float4*)(g_agg1 + (size_t)db.x * HID) + q), v4);
    red_add_v4((float*)((float4*)(g_agg1 + (size_t)db.y * HID) + q), v5);
    red_add_v4((float*)((float4*)(g_agg1 + (size_t)db.z * HID) + q), v6);
    red_add_v4((float*)((float4*)(g_agg1 + (size_t)db.w * HID) + q), v7);
}

// ---------------------------------------------------------------------------
// 4) h2s = relu(dinv*(agg1 + h1s) + b1) * dinv — one float4 per thread
__global__ void k_relu(const float* __restrict__ b1) {
    int t = blockIdx.x * blockDim.x + threadIdx.x;
    if (t >= NN * HID / 4) return;
    int node = t >> 2, f4 = t & 3;
    float di = g_dinv[node];
    float4 a = ((const float4*)g_agg1)[t];
    float4 h = ((const float4*)g_h1s)[t];
    float4 b = __ldg((const float4*)b1 + f4);
    float4 r;
    r.x = fmaxf(di * (a.x + h.x) + b.x, 0.f) * di;
    r.y = fmaxf(di * (a.y + h.y) + b.y, 0.f) * di;
    r.z = fmaxf(di * (a.z + h.z) + b.z, 0.f) * di;
    r.w = fmaxf(di * (a.w + h.w) + b.w, 0.f) * di;
    ((float4*)g_h2s)[t] = r;
}

// ---------------------------------------------------------------------------
// 5) layer-2 scatter: agg2[dst] += h2s[src] — same 8-edge scheme
__global__ void k_scat2(const int* __restrict__ ei) {
    int t = blockIdx.x * blockDim.x + threadIdx.x;
    int q = t & 3;
    int g = t >> 2;
    if (g >= EMAX / 8) return;
    int4 sa = __ldg((const int4*)ei + g * 2);
    int4 sb = __ldg((const int4*)ei + g * 2 + 1);
    int4 da = __ldg((const int4*)(ei + EMAX) + g * 2);
    int4 db = __ldg((const int4*)(ei + EMAX) + g * 2 + 1);
    float4 v0 = ((const float4*)(g_h2s + (size_t)sa.x * HID))[q];
    float4 v1 = ((const float4*)(g_h2s + (size_t)sa.y * HID))[q];
    float4 v2 = ((const float4*)(g_h2s + (size_t)sa.z * HID))[q];
    float4 v3 = ((const float4*)(g_h2s + (size_t)sa.w * HID))[q];
    float4 v4 = ((const float4*)(g_h2s + (size_t)sb.x * HID))[q];
    float4 v5 = ((const float4*)(g_h2s + (size_t)sb.y * HID))[q];
    float4 v6 = ((const float4*)(g_h2s + (size_t)sb.z * HID))[q];
    float4 v7 = ((const float4*)(g_h2s + (size_t)sb.w * HID))[q];
    red_add_v4((float*)((float4*)(g_agg2 + (size_t)da.x * HID) + q), v0);
    red_add_v4((float*)((float4*)(g_agg2 + (size_t)da.y * HID) + q), v1);
    red_add_v4((float*)((float4*)(g_agg2 + (size_t)da.z * HID) + q), v2);
    red_add_v4((float*)((float4*)(g_agg2 + (size_t)da.w * HID) + q), v3);
    red_add_v4((float*)((float4*)(g_agg2 + (size_t)db.x * HID) + q), v4);
    red_add_v4((float*)((float4*)(g_agg2 + (size_t)db.y * HID) + q), v5);
    red_add_v4((float*)((float4*)(g_agg2 + (size_t)db.z * HID) + q), v6);
    red_add_v4((float*)((float4*)(g_agg2 + (size_t)db.w * HID) + q), v7);
}

// ---------------------------------------------------------------------------
// 6) out = (dinv*(agg2 + h2s)) @ W2 + b2 — 64 nodes / 512-thread block.
//    Tail: zero g_cnt rows for the next invocation (self-restoring state).
#define VS_STRIDE 17
__global__ __launch_bounds__(512) void k_out(const float* __restrict__ W2,
                                             const float* __restrict__ b2,
                                             float* __restrict__ out) {
    __shared__ float wsh[HID * FIN];
    __shared__ float vsh[64 * VS_STRIDE];
    __shared__ float b2s[FIN];
    int node0 = blockIdx.x * 64;
    int tid = threadIdx.x;

    for (int i4 = tid; i4 < HID * FIN / 4; i4 += 512)
        ((float4*)wsh)[i4] = __ldg((const float4*)W2 + i4);
    if (tid < FIN) b2s[tid] = __ldg(&b2[tid]);
    for (int i = tid; i < 64 * HID; i += 512) {
        int nl = i >> 4, f = i & 15;
        int node = node0 + nl;
        float v = 0.f;
        if (node < NN) {
            int gi = node * HID + f;
            v = g_dinv[node] * (g_agg2[gi] + g_h2s[gi]);
        }
        vsh[nl * VS_STRIDE + f] = v;
    }
    // tail: reset histogram for next call
    if (tid < 64) {
        int node = node0 + tid;
        if (node < NN) g_cnt[node] = 0;
    }
    __syncthreads();

    int n = tid >> 3, og = tid & 7;
    int node = node0 + n;
    if (node >= NN) return;

    float acc[4][4];
    #pragma unroll
    for (int j = 0; j < 4; j++)
        #pragma unroll
        for (int i = 0; i < 4; i++)
            acc[j][i] = b2s[og * 4 + 32 * j + i];

    #pragma unroll
    for (int k = 0; k < HID; k++) {
        float v = vsh[n * VS_STRIDE + k];
        #pragma unroll
        for (int j = 0; j < 4; j++) {
            float4 w = *(const float4*)&wsh[k * FIN + og * 4 + 32 * j];
            acc[j][0] += v * w.x;  acc[j][1] += v * w.y;
            acc[j][2] += v * w.z;  acc[j][3] += v * w.w;
        }
    }
    float* orow = out + (size_t)node * FIN;
    #pragma unroll
    for (int j = 0; j < 4; j++)
        *(float4*)&orow[og * 4 + 32 * j] =
            make_float4(acc[j][0], acc[j][1], acc[j][2], acc[j][3]);
}

// ---------------------------------------------------------------------------
extern "C" void kernel_launch(void* const* d_in, const int* in_sizes, int n_in,
                              void* d_out, int out_size) {
    // Binding proven in R9: 0:x  1:edge_index(int32 [2,E])  2:W1  3:b1  4:W2  5:b2
    const float* x  = (const float*)d_in[0];
    const int*   ei = (const int*)d_in[1];
    const float* W1 = (const float*)d_in[2];
    const float* b1 = (const float*)d_in[3];
    const float* W2 = (const float*)d_in[4];
    const float* b2 = (const float*)d_in[5];
    float* out = (float*)d_out;

    k_deg  <<<(EMAX / 4 + 255) / 256, 256>>>(ei);
    k_mm1  <<<(NN + 31) / 32, 256>>>(x, W1);
    k_scat1<<<(EMAX / 2 + 255) / 256, 256>>>(ei);
    k_relu <<<(NN * HID / 4 + 255) / 256, 256>>>(b1);
    k_scat2<<<(EMAX / 2 + 255) / 256, 256>>>(ei);
    k_out  <<<(NN + 63) / 64, 512>>>(W2, b2, out);
}